// round 5
// baseline (speedup 1.0000x reference)
#include <cuda_runtime.h>
#include <cuda_bf16.h>
#include <cstdint>

#define N_IMG 64
#define IMG_ELEMS (3 * 512 * 512)          // 786432
#define TOTAL_ELEMS (N_IMG * IMG_ELEMS)    // 50331648
#define BINS 256

// ---- minmax geometry ----
#define MM_THREADS 256
#define MM_CHUNK   16384
#define MM_BPI     (IMG_ELEMS / MM_CHUNK)        // 48
#define MM_BLOCKS  (TOTAL_ELEMS / MM_CHUNK)      // 3072
#define MM_ITERS   (MM_CHUNK / 4 / MM_THREADS)   // 16

// ---- hist geometry (per-thread private smem hist, u8, bank == lane) ----
#define H_THREADS  192                            // 6 warps
#define H_CHUNK    24576                          // 128 elems/thread -> u8 counts safe
#define H_BPI      (IMG_ELEMS / H_CHUNK)          // 32
#define H_BLOCKS   (TOTAL_ELEMS / H_CHUNK)        // 2048
#define H_ITERS    (H_CHUNK / 4 / H_THREADS)      // 32
#define H_WORDS    (H_THREADS * BINS / 4)         // 12288 u32 words = 48 KB

// ---- gather geometry (8 idx bytes / thread / iter) ----
#define G_THREADS  256
#define G_CHUNK    16384
#define G_BPI      (IMG_ELEMS / G_CHUNK)          // 48
#define G_BLOCKS   (TOTAL_ELEMS / G_CHUNK)        // 3072
#define G_ITERS    (G_CHUNK / 8 / G_THREADS)      // 8

// ---------------- device scratch ----------------------------------------------
__device__ unsigned char g_idx[TOTAL_ELEMS];          // 48 MB bucket indices
__device__ unsigned int  g_minmax[2 * N_IMG];
__device__ int           g_hist[N_IMG * BINS];

__device__ __forceinline__ unsigned fenc(float f) {
    unsigned u = __float_as_uint(f);
    return (u & 0x80000000u) ? ~u : (u | 0x80000000u);
}
__device__ __forceinline__ float fdec(unsigned u) {
    u = (u & 0x80000000u) ? (u ^ 0x80000000u) : ~u;
    return __uint_as_float(u);
}

// ---------------- k0: reset scratch -------------------------------------------
__global__ void k_init() {
    int gt = blockIdx.x * 256 + threadIdx.x;     // 64*256 = 16384 = N_IMG*BINS
    g_hist[gt] = 0;
    if (gt < N_IMG) {
        g_minmax[gt] = 0xFFFFFFFFu;
        g_minmax[N_IMG + gt] = 0u;
    }
}

// ---------------- k1: per-image min/max ---------------------------------------
__global__ void __launch_bounds__(MM_THREADS) k_minmax(const float4* __restrict__ x) {
    int b = blockIdx.x, t = threadIdx.x;
    int img = b / MM_BPI;
    int base4 = b * (MM_CHUNK / 4);
    float mn = 3.4e38f, mx = -3.4e38f;
#pragma unroll
    for (int i = 0; i < MM_ITERS; i++) {
        float4 v = x[base4 + i * MM_THREADS + t];
        mn = fminf(mn, fminf(fminf(v.x, v.y), fminf(v.z, v.w)));
        mx = fmaxf(mx, fmaxf(fmaxf(v.x, v.y), fmaxf(v.z, v.w)));
    }
#pragma unroll
    for (int o = 16; o > 0; o >>= 1) {
        mn = fminf(mn, __shfl_xor_sync(0xffffffffu, mn, o));
        mx = fmaxf(mx, __shfl_xor_sync(0xffffffffu, mx, o));
    }
    __shared__ float smn[MM_THREADS / 32], smx[MM_THREADS / 32];
    int w = t >> 5;
    if ((t & 31) == 0) { smn[w] = mn; smx[w] = mx; }
    __syncthreads();
    if (t == 0) {
#pragma unroll
        for (int i = 1; i < MM_THREADS / 32; i++) {
            mn = fminf(mn, smn[i]);
            mx = fmaxf(mx, smx[i]);
        }
        atomicMin(&g_minmax[img], fenc(mn));
        atomicMax(&g_minmax[N_IMG + img], fenc(mx));
    }
}

// ---------------- k2: per-thread private hist, bank == lane (ZERO conflicts) --
__global__ void __launch_bounds__(H_THREADS) k_hist(const float4* __restrict__ x) {
    __shared__ uint32_t shw[H_WORDS];                    // 48 KB
    unsigned char* sh = reinterpret_cast<unsigned char*>(shw);

    int b = blockIdx.x, t = threadIdx.x;
    int img = b / H_BPI;
    unsigned lane = t & 31u;
    unsigned wreg = (unsigned)(t >> 5);                  // warp id 0..5

    uint4* shv = reinterpret_cast<uint4*>(shw);
#pragma unroll
    for (int i = 0; i < H_WORDS / 4 / H_THREADS; i++)
        shv[t + i * H_THREADS] = make_uint4(0, 0, 0, 0);

    float mn = fdec(g_minmax[img]);
    float mx = fdec(g_minmax[N_IMG + img]);
    float inv = 1.0f / (mx - mn + 1e-8f);
    __syncthreads();

    int base4 = b * (H_CHUNK / 4);
    uchar4* gi = reinterpret_cast<uchar4*>(g_idx);
    unsigned cbase = wreg * 8192u + lane * 4u;           // bank == lane column

#pragma unroll 8
    for (int i = 0; i < H_ITERS; i++) {
        // last read of x: evict-first so L2 keeps g_idx resident
        float4 v = __ldcs(&x[base4 + i * H_THREADS + t]);
        unsigned b0 = (unsigned)(int)fminf(fmaxf((v.x - mn) * 255.0f * inv, 0.0f), 255.0f);
        unsigned b1 = (unsigned)(int)fminf(fmaxf((v.y - mn) * 255.0f * inv, 0.0f), 255.0f);
        unsigned b2 = (unsigned)(int)fminf(fmaxf((v.z - mn) * 255.0f * inv, 0.0f), 255.0f);
        unsigned b3 = (unsigned)(int)fminf(fmaxf((v.w - mn) * 255.0f * inv, 0.0f), 255.0f);
        gi[base4 + i * H_THREADS + t] =
            make_uchar4((unsigned char)b0, (unsigned char)b1,
                        (unsigned char)b2, (unsigned char)b3);
        sh[cbase + (b0 >> 2) * 128u + (b0 & 3u)]++;
        sh[cbase + (b1 >> 2) * 128u + (b1 & 3u)]++;
        sh[cbase + (b2 >> 2) * 128u + (b2 & 3u)]++;
        sh[cbase + (b3 >> 2) * 128u + (b3 & 3u)]++;
    }
    __syncthreads();

    // Reduce: thread (q = t&63, g = t>>6) sums quad q over warp-regions {2g, 2g+1}
    int q = t & 63, g = t >> 6;
    uint32_t s02 = 0, s13 = 0;                           // packed u16 pairs
#pragma unroll
    for (int r = 0; r < 2; r++) {
        int w2 = g * 2 + r;
#pragma unroll 8
        for (int i = 0; i < 32; i++) {
            int l = (i + t) & 31;
            uint32_t v = shw[w2 * 2048 + q * 32 + l];
            s02 += v & 0x00FF00FFu;
            s13 += (v >> 8) & 0x00FF00FFu;
        }
    }
    __syncthreads();
    shw[t * 2] = s02;
    shw[t * 2 + 1] = s13;
    __syncthreads();
    if (t < 64) {
        uint32_t a02 = shw[t * 2]     + shw[(64 + t) * 2]     + shw[(128 + t) * 2];
        uint32_t a13 = shw[t * 2 + 1] + shw[(64 + t) * 2 + 1] + shw[(128 + t) * 2 + 1];
        int base = img * BINS + t * 4;
        atomicAdd(&g_hist[base + 0], (int)(a02 & 0xFFFFu));
        atomicAdd(&g_hist[base + 1], (int)(a13 & 0xFFFFu));
        atomicAdd(&g_hist[base + 2], (int)(a02 >> 16));
        atomicAdd(&g_hist[base + 3], (int)(a13 >> 16));
    }
}

// ---------------- k3: cdf scan + gather, 4-way replicated LUT (4 KB) ----------
// word = bin*4 + (lane&3): identical bins in different lane-quarters -> distinct
// banks; conflicts need bins differing by a multiple of 8 within one quarter.
__global__ void __launch_bounds__(G_THREADS) k_gather(float4* __restrict__ out) {
    int b = blockIdx.x, t = threadIdx.x;
    int img = b / G_BPI;
    unsigned lq = (unsigned)t & 3u;                      // lane quarter slot
    __shared__ float lut4[BINS * 4];
    {
        int lane = t & 31, w = t >> 5;
        int s = g_hist[img * BINS + t];
#pragma unroll
        for (int o = 1; o < 32; o <<= 1) {
            int n = __shfl_up_sync(0xffffffffu, s, (unsigned)o);
            if (lane >= o) s += n;
        }
        __shared__ int wsum[8], woff[8];
        if (lane == 31) wsum[w] = s;
        __syncthreads();
        if (t == 0) {
            int acc = 0;
#pragma unroll
            for (int i = 0; i < 8; i++) { woff[i] = acc; acc += wsum[i]; }
        }
        __syncthreads();
        int cdf = s + woff[w];                   // inclusive scan, exact int
        __shared__ float sc0, stot;
        if (t == 0)   sc0  = (float)cdf;
        if (t == 255) stot = (float)cdf;
        __syncthreads();
        float val = ((float)cdf - sc0) / (stot - sc0 + 1e-8f);
#pragma unroll
        for (int r = 0; r < 4; r++) lut4[t * 4 + r] = val;
        __syncthreads();
    }
    int base8 = b * (G_CHUNK / 8);                       // uint2 (8 idx bytes) units
    const uint2* gi = reinterpret_cast<const uint2*>(g_idx);
    float4* o4 = out;
#pragma unroll
    for (int i = 0; i < G_ITERS; i++) {
        uint2 u = gi[base8 + i * G_THREADS + t];
        float4 r0, r1;
        r0.x = lut4[((u.x      ) & 0xFFu) * 4u + lq];
        r0.y = lut4[((u.x >>  8) & 0xFFu) * 4u + lq];
        r0.z = lut4[((u.x >> 16) & 0xFFu) * 4u + lq];
        r0.w = lut4[((u.x >> 24)        ) * 4u + lq];
        r1.x = lut4[((u.y      ) & 0xFFu) * 4u + lq];
        r1.y = lut4[((u.y >>  8) & 0xFFu) * 4u + lq];
        r1.z = lut4[((u.y >> 16) & 0xFFu) * 4u + lq];
        r1.w = lut4[((u.y >> 24)        ) * 4u + lq];
        // write-once streaming: evict-first, keep g_idx in L2
        __stcs(&o4[(base8 + i * G_THREADS + t) * 2 + 0], r0);
        __stcs(&o4[(base8 + i * G_THREADS + t) * 2 + 1], r1);
    }
}

// ---------------- launch -------------------------------------------------------
extern "C" void kernel_launch(void* const* d_in, const int* in_sizes, int n_in,
                              void* d_out, int out_size) {
    const float4* x = reinterpret_cast<const float4*>(d_in[0]);
    float4* out = reinterpret_cast<float4*>(d_out);

    k_init  <<<N_IMG, 256>>>();
    k_minmax<<<MM_BLOCKS, MM_THREADS>>>(x);
    k_hist  <<<H_BLOCKS, H_THREADS>>>(x);
    k_gather<<<G_BLOCKS, G_THREADS>>>(out);
}

// round 6
// speedup vs baseline: 1.2056x; 1.2056x over previous
#include <cuda_runtime.h>
#include <cuda_bf16.h>
#include <cstdint>

#define N_IMG 64
#define IMG_ELEMS (3 * 512 * 512)          // 786432
#define BINS 256

#define THREADS 192                         // 6 warps
#define CHUNK   24576                       // elems per block; 128/thread -> u8 safe
#define BPI     (IMG_ELEMS / CHUNK)         // 32 blocks per image
#define NBLOCKS (N_IMG * BPI)               // 2048
#define ITERS   (CHUNK / 4 / THREADS)       // 32 float4 iters
#define H_WORDS (THREADS * BINS / 4)        // 12288 u32 = 48 KB private hists
#define IDX_WORDS (CHUNK / 4)               // 6144 u32 = 24 KB idx bytes
#define DYN_SMEM ((H_WORDS + IDX_WORDS) * 4)  // 73728 B

// ---------------- global coordination state -----------------------------------
__device__ unsigned int g_minmax[2 * N_IMG];   // enc(min), enc(max)
__device__ int g_hist[N_IMG * BINS];
__device__ int g_cnt1[N_IMG];                  // minmax arrivals
__device__ int g_cnt2[N_IMG];                  // hist arrivals

__device__ __forceinline__ unsigned fenc(float f) {
    unsigned u = __float_as_uint(f);
    return (u & 0x80000000u) ? ~u : (u | 0x80000000u);
}
__device__ __forceinline__ float fdec(unsigned u) {
    u = (u & 0x80000000u) ? (u ^ 0x80000000u) : ~u;
    return __uint_as_float(u);
}

// ---------------- k0: reset all coordination state (every replay!) ------------
__global__ void k_init() {
    int gt = blockIdx.x * 256 + threadIdx.x;       // 16384 = N_IMG*BINS
    g_hist[gt] = 0;
    if (gt < N_IMG) {
        g_minmax[gt] = 0xFFFFFFFFu;
        g_minmax[N_IMG + gt] = 0u;
        g_cnt1[gt] = 0;
        g_cnt2[gt] = 0;
    }
}

// ---------------- fused equalize: minmax -> hist -> cdf -> gather -------------
__global__ void __launch_bounds__(THREADS, 3)
k_equalize(const float4* __restrict__ x, float4* __restrict__ out) {
    extern __shared__ uint32_t smem[];
    uint32_t* shw  = smem;                          // 48 KB private hists / lut
    uint32_t* sidx = smem + H_WORDS;                // 24 KB idx bytes
    unsigned char* sh = reinterpret_cast<unsigned char*>(shw);
    float* lutf = reinterpret_cast<float*>(shw);

    int b = blockIdx.x, t = threadIdx.x;
    int img = b / BPI;
    int base4 = b * (CHUNK / 4);
    unsigned lane = t & 31u;
    unsigned wreg = (unsigned)(t >> 5);

    __shared__ float smn[6], smx[6];

    // ---- phase 1: block minmax over my chunk (x stays L2-resident) ----
    float mn = 3.4e38f, mx = -3.4e38f;
#pragma unroll 8
    for (int i = 0; i < ITERS; i++) {
        float4 v = x[base4 + i * THREADS + t];
        mn = fminf(mn, fminf(fminf(v.x, v.y), fminf(v.z, v.w)));
        mx = fmaxf(mx, fmaxf(fmaxf(v.x, v.y), fmaxf(v.z, v.w)));
    }
#pragma unroll
    for (int o = 16; o > 0; o >>= 1) {
        mn = fminf(mn, __shfl_xor_sync(0xffffffffu, mn, o));
        mx = fmaxf(mx, __shfl_xor_sync(0xffffffffu, mx, o));
    }
    if (lane == 0) { smn[wreg] = mn; smx[wreg] = mx; }
    __syncthreads();
    if (t == 0) {
#pragma unroll
        for (int i = 1; i < 6; i++) {
            mn = fminf(mn, smn[i]);
            mx = fmaxf(mx, smx[i]);
        }
        atomicMin(&g_minmax[img], fenc(mn));
        atomicMax(&g_minmax[N_IMG + img], fenc(mx));
        __threadfence();
        atomicAdd(&g_cnt1[img], 1);
    }
    // overlap: everyone zeros the private hists while thread 0 will spin
    uint4* shv = reinterpret_cast<uint4*>(shw);
#pragma unroll
    for (int i = 0; i < H_WORDS / 4 / THREADS; i++)
        shv[t + i * THREADS] = make_uint4(0, 0, 0, 0);
    if (t == 0) {
        while (*((volatile int*)&g_cnt1[img]) < BPI) __nanosleep(64);
        __threadfence();
    }
    __syncthreads();

    float gmn = fdec(__ldcg(&g_minmax[img]));
    float gmx = fdec(__ldcg(&g_minmax[N_IMG + img]));
    float inv = 1.0f / (gmx - gmn + 1e-8f);

    // ---- phase 2: bucket (L2-hot re-read), idx -> smem, bank==lane hists ----
    unsigned cbase = wreg * 8192u + lane * 4u;
#pragma unroll 8
    for (int i = 0; i < ITERS; i++) {
        float4 v = __ldcs(&x[base4 + i * THREADS + t]);   // last read: evict
        unsigned b0 = (unsigned)(int)fminf(fmaxf((v.x - gmn) * 255.0f * inv, 0.0f), 255.0f);
        unsigned b1 = (unsigned)(int)fminf(fmaxf((v.y - gmn) * 255.0f * inv, 0.0f), 255.0f);
        unsigned b2 = (unsigned)(int)fminf(fmaxf((v.z - gmn) * 255.0f * inv, 0.0f), 255.0f);
        unsigned b3 = (unsigned)(int)fminf(fmaxf((v.w - gmn) * 255.0f * inv, 0.0f), 255.0f);
        sidx[i * THREADS + t] = b0 | (b1 << 8) | (b2 << 16) | (b3 << 24);
        sh[cbase + (b0 >> 2) * 128u + (b0 & 3u)]++;
        sh[cbase + (b1 >> 2) * 128u + (b1 & 3u)]++;
        sh[cbase + (b2 >> 2) * 128u + (b2 & 3u)]++;
        sh[cbase + (b3 >> 2) * 128u + (b3 & 3u)]++;
    }
    __syncthreads();

    // ---- phase 3: reduce private hists -> g_hist (lane-staggered, no conflicts)
    {
        int q = t & 63, g = t >> 6;                       // g in 0..2
        uint32_t s02 = 0, s13 = 0;
#pragma unroll
        for (int r = 0; r < 2; r++) {
            int w2 = g * 2 + r;
#pragma unroll 8
            for (int i = 0; i < 32; i++) {
                int l = (i + t) & 31;
                uint32_t v = shw[w2 * 2048 + q * 32 + l];
                s02 += v & 0x00FF00FFu;
                s13 += (v >> 8) & 0x00FF00FFu;
            }
        }
        __syncthreads();
        shw[t * 2] = s02;
        shw[t * 2 + 1] = s13;
        __syncthreads();
        if (t < 64) {
            uint32_t a02 = shw[t * 2]     + shw[(64 + t) * 2]     + shw[(128 + t) * 2];
            uint32_t a13 = shw[t * 2 + 1] + shw[(64 + t) * 2 + 1] + shw[(128 + t) * 2 + 1];
            int base = img * BINS + t * 4;
            atomicAdd(&g_hist[base + 0], (int)(a02 & 0xFFFFu));
            atomicAdd(&g_hist[base + 1], (int)(a13 & 0xFFFFu));
            atomicAdd(&g_hist[base + 2], (int)(a02 >> 16));
            atomicAdd(&g_hist[base + 3], (int)(a13 >> 16));
        }
        __syncthreads();                                   // hist atomics issued
        if (t == 0) {
            __threadfence();
            atomicAdd(&g_cnt2[img], 1);
            while (*((volatile int*)&g_cnt2[img]) < BPI) __nanosleep(64);
            __threadfence();
        }
        __syncthreads();
    }

    // ---- phase 4a: warp 0 scans the 256-bin cdf, LUT into smem (reuses shw) --
    if (t < 32) {
        int loc[8];
        int s = 0;
#pragma unroll
        for (int j = 0; j < 8; j++) {
            s += __ldcg(&g_hist[img * BINS + t * 8 + j]);
            loc[j] = s;                                    // inclusive within lane
        }
        int sc = s;
#pragma unroll
        for (int o = 1; o < 32; o <<= 1) {
            int n = __shfl_up_sync(0xffffffffu, sc, (unsigned)o);
            if (t >= o) sc += n;
        }
        int excl = sc - s;                                 // exclusive lane offset
        float c0  = (float)__shfl_sync(0xffffffffu, loc[0], 0);   // cdf[0]
        float ctot = (float)__shfl_sync(0xffffffffu, sc, 31);     // cdf[255]
        float dinv = 1.0f / (ctot - c0 + 1e-8f);
#pragma unroll
        for (int j = 0; j < 8; j++)
            lutf[t * 8 + j] = ((float)(excl + loc[j]) - c0) * dinv;
    }
    __syncthreads();

    // ---- phase 4b: gather from smem idx, stream out ----
#pragma unroll 8
    for (int i = 0; i < ITERS; i++) {
        uint32_t u = sidx[i * THREADS + t];
        float4 r;
        r.x = lutf[u & 0xFFu];
        r.y = lutf[(u >> 8) & 0xFFu];
        r.z = lutf[(u >> 16) & 0xFFu];
        r.w = lutf[u >> 24];
        __stcs(&out[base4 + i * THREADS + t], r);
    }
}

// ---------------- launch -------------------------------------------------------
extern "C" void kernel_launch(void* const* d_in, const int* in_sizes, int n_in,
                              void* d_out, int out_size) {
    const float4* x = reinterpret_cast<const float4*>(d_in[0]);
    float4* out = reinterpret_cast<float4*>(d_out);

    static bool configured = false;
    if (!configured) {
        cudaFuncSetAttribute(k_equalize,
                             cudaFuncAttributeMaxDynamicSharedMemorySize, DYN_SMEM);
        configured = true;
    }
    k_init<<<N_IMG, 256>>>();
    k_equalize<<<NBLOCKS, THREADS, DYN_SMEM>>>(x, out);
}